// round 5
// baseline (speedup 1.0000x reference)
#include <cuda_runtime.h>
#include <cuda_bf16.h>
#include <cstdint>

// Problem constants
#define NVOX   262144
#define BATCH  4
#define NBOX   32
#define C3D    64
#define C2D    256
#define MIDC   128
#define OUTC   64
#define IMH    96
#define IMW    312
#define HW     (IMH*IMW)        // 29952

// Intermediate image features, NHWC: [b][pix][mid], 61.3 MB
__device__ __align__(256) float g_itbuf[(size_t)BATCH * HW * MIDC];

// ---------------------------------------------------------------------------
// Kernel 1: it = relu(bn(conv1x1(image)))  -> g_itbuf (NHWC)
// GEMM: out[pix][mid] = sum_c img[b][c][pix] * w_it[mid][c]
// Tile: 128 pixels x 128 mids, k-chunks of 64. 256 threads, 8x8 per thread.
// ---------------------------------------------------------------------------
__global__ __launch_bounds__(256) void img_gemm_kernel(
    const float* __restrict__ img,    // [B][C2D][H][W]
    const float* __restrict__ w_it,   // [MID][C2D]
    const float* __restrict__ b_it,
    const float* __restrict__ gam,
    const float* __restrict__ bet,
    const float* __restrict__ mu,
    const float* __restrict__ var)
{
    extern __shared__ float sm1[];
    float* sImg = sm1;                // [64][128]
    float* sW   = sm1 + 64*128;       // [64][128] (k-major, transposed)
    float* sS   = sm1 + 2*64*128;     // [128]
    float* sO   = sS + 128;           // [128]

    const int tid = threadIdx.x;
    const int b   = blockIdx.y;
    const int hw0 = blockIdx.x * 128;

    if (tid < 128) {
        float s = gam[tid] * rsqrtf(var[tid] + 1e-5f);
        sS[tid] = s;
        sO[tid] = (b_it[tid] - mu[tid]) * s + bet[tid];
    }

    const int rowg = (tid >> 4) * 8;   // pixel group
    const int colg = (tid & 15) * 8;   // mid group
    float acc[8][8];
    #pragma unroll
    for (int i = 0; i < 8; i++)
        #pragma unroll
        for (int j = 0; j < 8; j++) acc[i][j] = 0.f;

    for (int kc = 0; kc < C2D; kc += 64) {
        __syncthreads();
        // load image chunk [64 k][128 pix], coalesced
        #pragma unroll
        for (int i = 0; i < 8; i++) {
            int idx = tid + i*256;
            int kk = idx >> 5, c4 = (idx & 31) << 2;
            float4 f = *(const float4*)&img[(size_t)((b*C2D + kc + kk))*HW + hw0 + c4];
            *(float4*)&sImg[kk*128 + c4] = f;
        }
        // load weight chunk transposed: sW[k][mid]
        #pragma unroll
        for (int i = 0; i < 8; i++) {
            int idx = tid + i*256;
            int mid = idx & 127, kq = idx >> 7;     // kq in 0..15
            float4 f = *(const float4*)&w_it[mid*C2D + kc + kq*4];
            sW[(kq*4+0)*128 + mid] = f.x;
            sW[(kq*4+1)*128 + mid] = f.y;
            sW[(kq*4+2)*128 + mid] = f.z;
            sW[(kq*4+3)*128 + mid] = f.w;
        }
        __syncthreads();
        #pragma unroll 16
        for (int kk = 0; kk < 64; kk++) {
            float a[8], bb[8];
            *(float4*)(a)    = *(const float4*)&sImg[kk*128 + rowg];
            *(float4*)(a+4)  = *(const float4*)&sImg[kk*128 + rowg + 4];
            *(float4*)(bb)   = *(const float4*)&sW[kk*128 + colg];
            *(float4*)(bb+4) = *(const float4*)&sW[kk*128 + colg + 4];
            #pragma unroll
            for (int i = 0; i < 8; i++)
                #pragma unroll
                for (int j = 0; j < 8; j++)
                    acc[i][j] = fmaf(a[i], bb[j], acc[i][j]);
        }
    }
    // epilogue: bn + relu, store NHWC
    #pragma unroll
    for (int i = 0; i < 8; i++) {
        size_t base = ((size_t)b*HW + hw0 + rowg + i) * MIDC + colg;
        float4 o0, o1;
        o0.x = fmaxf(fmaf(acc[i][0], sS[colg+0], sO[colg+0]), 0.f);
        o0.y = fmaxf(fmaf(acc[i][1], sS[colg+1], sO[colg+1]), 0.f);
        o0.z = fmaxf(fmaf(acc[i][2], sS[colg+2], sO[colg+2]), 0.f);
        o0.w = fmaxf(fmaf(acc[i][3], sS[colg+3], sO[colg+3]), 0.f);
        o1.x = fmaxf(fmaf(acc[i][4], sS[colg+4], sO[colg+4]), 0.f);
        o1.y = fmaxf(fmaf(acc[i][5], sS[colg+5], sO[colg+5]), 0.f);
        o1.z = fmaxf(fmaf(acc[i][6], sS[colg+6], sO[colg+6]), 0.f);
        o1.w = fmaxf(fmaf(acc[i][7], sS[colg+7], sO[colg+7]), 0.f);
        *(float4*)&g_itbuf[base]     = o0;
        *(float4*)&g_itbuf[base + 4] = o1;
    }
}

// ---------------------------------------------------------------------------
// Kernel 2: per-128-voxel-tile fused pipeline
//   stage0: boxes/classes/bn-consts, per-voxel w3d + bilinear params
//   stage1: vt = relu(bn(vf @ w_vt^T)) * w3d    -> fusedT[0..127][row]
//   stage1b: bilinear sample * (1-w3d)          -> fusedT[128..255][row]
//   stage2: out = relu(bn(fusedT^T @ w_f^T))
// PITCH_F = 132 (multiple of 4 -> aligned LDS.128 in stage 2).
// Stage-1 epilogue stores are STS.128 along rows -> conflict-free.
// ---------------------------------------------------------------------------
#define PITCH_F 132
#define SM2_FLOATS (256*PITCH_F + 16640 + 896 + 128 + 128 + 64 + 64 + 128 + 512 + 128 + 512)

__global__ __launch_bounds__(512) void fuse_kernel(
    const float* __restrict__ vf,        // [N][64]
    const int*   __restrict__ coords,    // [N][4]  (b,z,y,x)
    const float* __restrict__ gt_boxes,  // [4][32][7]
    const int*   __restrict__ gt_classes,// [4][32]
    const float* __restrict__ w_vt,      // [128][64]
    const float* __restrict__ b_vt,
    const float* __restrict__ g_vt,
    const float* __restrict__ be_vt,
    const float* __restrict__ m_vt,
    const float* __restrict__ v_vt,
    const float* __restrict__ w_f,       // [64][256]
    const float* __restrict__ b_f,
    const float* __restrict__ g_f,
    const float* __restrict__ be_f,
    const float* __restrict__ m_f,
    const float* __restrict__ v_f,
    float* __restrict__ out)             // [N][64]
{
    extern __shared__ float sm[];
    float* fusedT  = sm;                       // [256][PITCH_F]
    float* scratch = sm + 256*PITCH_F;         // 16640 floats
    float* vfT     = scratch;                  // [64][132]
    float* wvtT    = scratch + 64*132;         // [64][128]
    float* wfT     = scratch;                  // [256][64] (aliased, after sync2)
    float* boxes_s = sm + 256*PITCH_F + 16640; // 896
    float* sA      = boxes_s + 896;            // 128
    float* oA      = sA + 128;                 // 128
    float* sF      = oA + 128;                 // 64
    float* oF      = sF + 64;                  // 64
    float* w3d_s   = oF + 64;                  // 128
    float* cw_s    = w3d_s + 128;              // 512 (4 corner weights/voxel)
    int*   cls_s   = (int*)(cw_s + 512);       // 128
    int*   coff_s  = cls_s + 128;              // 512 (4 corner offsets/voxel)

    const int tid = threadIdx.x;
    const int v0  = blockIdx.x * 128;

    // ---- stage 0 loads ----
    for (int i = tid; i < 896; i += 512) boxes_s[i] = gt_boxes[i];
    if (tid < 128) {
        cls_s[tid] = gt_classes[tid];
        float s = g_vt[tid] * rsqrtf(v_vt[tid] + 1e-5f);
        sA[tid] = s;
        oA[tid] = (b_vt[tid] - m_vt[tid]) * s + be_vt[tid];
    } else if (tid < 192) {
        int c = tid - 128;
        float s = g_f[c] * rsqrtf(v_f[c] + 1e-5f);
        sF[c] = s;
        oF[c] = (b_f[c] - m_f[c]) * s + be_f[c];
    }
    // vf tile transposed: vfT[k][row], pitch 132
    #pragma unroll
    for (int i = 0; i < 4; i++) {
        int idx = tid + i*512;
        int r = idx >> 4, k4 = (idx & 15) << 2;
        float4 f = *(const float4*)&vf[(size_t)(v0 + r)*C3D + k4];
        vfT[(k4+0)*132 + r] = f.x;
        vfT[(k4+1)*132 + r] = f.y;
        vfT[(k4+2)*132 + r] = f.z;
        vfT[(k4+3)*132 + r] = f.w;
    }
    // w_vt transposed: wvtT[k][mid], pitch 128
    #pragma unroll
    for (int i = 0; i < 4; i++) {
        int idx = tid + i*512;
        int mid = idx & 127, kq = idx >> 7;
        float4 f = *(const float4*)&w_vt[mid*C3D + kq*4];
        wvtT[(kq*4+0)*128 + mid] = f.x;
        wvtT[(kq*4+1)*128 + mid] = f.y;
        wvtT[(kq*4+2)*128 + mid] = f.z;
        wvtT[(kq*4+3)*128 + mid] = f.w;
    }
    __syncthreads();

    // ---- stage 0b: per-voxel scalar work ----
    if (tid < 128) {
        int4 c = *(const int4*)&coords[(size_t)(v0 + tid)*4];
        int b = c.x;
        float crx = (float)c.w * 0.05f;           // x
        float cry = (float)c.z * 0.05f - 40.f;    // y
        float crz = (float)c.y * 0.1f  - 3.f;     // z
        // class-aware weight via box membership (last box containing voxel)
        int last = -1;
        const float* bb = boxes_s + b*224;
        #pragma unroll
        for (int mi = 0; mi < NBOX; mi++) {
            const float* p = bb + mi*7;
            bool in = (fabsf(crx - p[0]) < p[3]*0.5f) &&
                      (fabsf(cry - p[1]) < p[4]*0.5f) &&
                      (fabsf(crz - p[2]) < p[5]*0.5f) &&
                      (p[3] > 0.f);
            if (in) last = mi;
        }
        float w3;
        if (last >= 0) {
            int cl = cls_s[b*NBOX + last];
            w3 = (cl == 0) ? 0.85f : ((cl == 1) ? 0.95f : 0.6f);
        } else w3 = 0.8f;
        w3d_s[tid] = w3;
        // bilinear sampling params
        float cx = crx + 0.025f;
        float cy = cry + 0.025f;
        float px = cx*10.f + (float)IMW*0.5f;
        float py = cy*10.f + (float)IMH*0.5f;
        float nx = fminf(fmaxf(px/(float)IMW*2.f - 1.f, -1.f), 1.f);
        float ny = fminf(fmaxf(py/(float)IMH*2.f - 1.f, -1.f), 1.f);
        float fx = ((nx + 1.f)*(float)IMW - 1.f)*0.5f;
        float fy = ((ny + 1.f)*(float)IMH - 1.f)*0.5f;
        float x0f = floorf(fx), y0f = floorf(fy);
        float wx = fx - x0f, wy = fy - y0f;
        int x0 = (int)x0f, y0 = (int)y0f;
        #pragma unroll
        for (int ci = 0; ci < 4; ci++) {
            int dx = ci & 1, dy = ci >> 1;
            int xi = x0 + dx, yi = y0 + dy;
            bool val = (xi >= 0) && (xi < IMW) && (yi >= 0) && (yi < IMH);
            int xc = min(max(xi, 0), IMW-1);
            int yc = min(max(yi, 0), IMH-1);
            float wgt = (dx ? wx : 1.f - wx) * (dy ? wy : 1.f - wy);
            cw_s[tid*4 + ci]   = val ? wgt : 0.f;
            coff_s[tid*4 + ci] = ((b*IMH + yc)*IMW + xc) * MIDC;
        }
    }

    // ---- stage 1: vt GEMM (128 rows x 128 mids, k=64) ----
    // thread (warp w, lane l): channels w*8..w*8+7, rows 4l..4l+3
    const int s1_w = tid >> 5;        // 0..15
    const int s1_l = tid & 31;        // lane
    float acc1[4][8];
    #pragma unroll
    for (int i = 0; i < 4; i++)
        #pragma unroll
        for (int j = 0; j < 8; j++) acc1[i][j] = 0.f;
    #pragma unroll 8
    for (int k = 0; k < 64; k++) {
        float4 a  = *(const float4*)&vfT[k*132 + 4*s1_l];
        float4 b0 = *(const float4*)&wvtT[k*128 + s1_w*8];
        float4 b1 = *(const float4*)&wvtT[k*128 + s1_w*8 + 4];
        float av[4] = {a.x, a.y, a.z, a.w};
        float bv[8] = {b0.x, b0.y, b0.z, b0.w, b1.x, b1.y, b1.z, b1.w};
        #pragma unroll
        for (int i = 0; i < 4; i++)
            #pragma unroll
            for (int j = 0; j < 8; j++)
                acc1[i][j] = fmaf(av[i], bv[j], acc1[i][j]);
    }
    __syncthreads();   // done with vfT/wvtT; w3d/cw/coff now visible to all

    // load w_f transposed into (aliased) scratch: wfT[k][o], pitch 64
    #pragma unroll
    for (int i = 0; i < 8; i++) {
        int idx = tid + i*512;
        int o = idx & 63, kq = idx >> 6;
        float4 f = *(const float4*)&w_f[o*256 + kq*4];
        wfT[(kq*4+0)*64 + o] = f.x;
        wfT[(kq*4+1)*64 + o] = f.y;
        wfT[(kq*4+2)*64 + o] = f.z;
        wfT[(kq*4+3)*64 + o] = f.w;
    }
    // stage 1 epilogue: bn+relu, * w3d, vectorized store to fusedT (k-major)
    {
        float w3v[4];
        #pragma unroll
        for (int i = 0; i < 4; i++) w3v[i] = w3d_s[4*s1_l + i];
        #pragma unroll
        for (int j = 0; j < 8; j++) {
            int cc = s1_w*8 + j;
            float s = sA[cc], o = oA[cc];
            float4 y;
            y.x = fmaxf(fmaf(acc1[0][j], s, o), 0.f) * w3v[0];
            y.y = fmaxf(fmaf(acc1[1][j], s, o), 0.f) * w3v[1];
            y.z = fmaxf(fmaf(acc1[2][j], s, o), 0.f) * w3v[2];
            y.w = fmaxf(fmaf(acc1[3][j], s, o), 0.f) * w3v[3];
            *(float4*)&fusedT[cc*PITCH_F + 4*s1_l] = y;
        }
    }

    // ---- stage 1b: bilinear sampling ----
    {
        int v  = tid & 127;
        int cb = (tid >> 7) * 32;  // channel base (4 thr/voxel, 32 ch each)
        float wim = 1.f - w3d_s[v];
        float4 acc4[8];
        #pragma unroll
        for (int j = 0; j < 8; j++) acc4[j] = make_float4(0.f, 0.f, 0.f, 0.f);
        #pragma unroll
        for (int ci = 0; ci < 4; ci++) {
            float wgt = cw_s[v*4 + ci] * wim;
            const float4* p = (const float4*)&g_itbuf[(size_t)coff_s[v*4 + ci] + cb];
            #pragma unroll
            for (int j = 0; j < 8; j++) {
                float4 f = p[j];
                acc4[j].x = fmaf(wgt, f.x, acc4[j].x);
                acc4[j].y = fmaf(wgt, f.y, acc4[j].y);
                acc4[j].z = fmaf(wgt, f.z, acc4[j].z);
                acc4[j].w = fmaf(wgt, f.w, acc4[j].w);
            }
        }
        #pragma unroll
        for (int j = 0; j < 8; j++) {
            int ch = 128 + cb + j*4;
            fusedT[(ch+0)*PITCH_F + v] = acc4[j].x;
            fusedT[(ch+1)*PITCH_F + v] = acc4[j].y;
            fusedT[(ch+2)*PITCH_F + v] = acc4[j].z;
            fusedT[(ch+3)*PITCH_F + v] = acc4[j].w;
        }
    }
    __syncthreads();

    // ---- stage 2: final GEMM (128 rows x 64 outs, k=256) ----
    {
        const int rowg = (tid >> 4) * 4;
        const int colg = (tid & 15) * 4;
        float acc[4][4];
        #pragma unroll
        for (int i = 0; i < 4; i++)
            #pragma unroll
            for (int j = 0; j < 4; j++) acc[i][j] = 0.f;
        #pragma unroll 8
        for (int k = 0; k < 256; k++) {
            float4 a  = *(const float4*)&fusedT[k*PITCH_F + rowg];
            float4 bv = *(const float4*)&wfT[k*64 + colg];
            acc[0][0] = fmaf(a.x, bv.x, acc[0][0]);
            acc[0][1] = fmaf(a.x, bv.y, acc[0][1]);
            acc[0][2] = fmaf(a.x, bv.z, acc[0][2]);
            acc[0][3] = fmaf(a.x, bv.w, acc[0][3]);
            acc[1][0] = fmaf(a.y, bv.x, acc[1][0]);
            acc[1][1] = fmaf(a.y, bv.y, acc[1][1]);
            acc[1][2] = fmaf(a.y, bv.z, acc[1][2]);
            acc[1][3] = fmaf(a.y, bv.w, acc[1][3]);
            acc[2][0] = fmaf(a.z, bv.x, acc[2][0]);
            acc[2][1] = fmaf(a.z, bv.y, acc[2][1]);
            acc[2][2] = fmaf(a.z, bv.z, acc[2][2]);
            acc[2][3] = fmaf(a.z, bv.w, acc[2][3]);
            acc[3][0] = fmaf(a.w, bv.x, acc[3][0]);
            acc[3][1] = fmaf(a.w, bv.y, acc[3][1]);
            acc[3][2] = fmaf(a.w, bv.z, acc[3][2]);
            acc[3][3] = fmaf(a.w, bv.w, acc[3][3]);
        }
        float s0 = sF[colg+0], s1 = sF[colg+1], s2 = sF[colg+2], s3 = sF[colg+3];
        float o0 = oF[colg+0], o1 = oF[colg+1], o2 = oF[colg+2], o3 = oF[colg+3];
        #pragma unroll
        for (int i = 0; i < 4; i++) {
            float4 o;
            o.x = fmaxf(fmaf(acc[i][0], s0, o0), 0.f);
            o.y = fmaxf(fmaf(acc[i][1], s1, o1), 0.f);
            o.z = fmaxf(fmaf(acc[i][2], s2, o2), 0.f);
            o.w = fmaxf(fmaf(acc[i][3], s3, o3), 0.f);
            *(float4*)&out[(size_t)(v0 + rowg + i)*OUTC + colg] = o;
        }
    }
}

// ---------------------------------------------------------------------------
extern "C" void kernel_launch(void* const* d_in, const int* in_sizes, int n_in,
                              void* d_out, int out_size)
{
    const float* vf       = (const float*)d_in[0];
    const int*   coords   = (const int*)  d_in[1];
    const float* img      = (const float*)d_in[2];
    const float* boxes    = (const float*)d_in[3];
    const int*   classes  = (const int*)  d_in[4];
    const float* w_vt     = (const float*)d_in[5];
    const float* b_vt     = (const float*)d_in[6];
    const float* g_vt     = (const float*)d_in[7];
    const float* be_vt    = (const float*)d_in[8];
    const float* m_vt     = (const float*)d_in[9];
    const float* v_vt     = (const float*)d_in[10];
    const float* w_it     = (const float*)d_in[11];
    const float* b_it     = (const float*)d_in[12];
    const float* g_itp    = (const float*)d_in[13];
    const float* be_it    = (const float*)d_in[14];
    const float* m_it     = (const float*)d_in[15];
    const float* v_it     = (const float*)d_in[16];
    const float* w_f      = (const float*)d_in[17];
    const float* b_f      = (const float*)d_in[18];
    const float* g_f      = (const float*)d_in[19];
    const float* be_f     = (const float*)d_in[20];
    const float* m_f      = (const float*)d_in[21];
    const float* v_f      = (const float*)d_in[22];
    float* out = (float*)d_out;

    const size_t smem1 = (size_t)(2*64*128 + 256) * sizeof(float);     // 66,560 B
    const size_t smem2 = (size_t)SM2_FLOATS * sizeof(float);           // ~212 KB
    cudaFuncSetAttribute(img_gemm_kernel,
                         cudaFuncAttributeMaxDynamicSharedMemorySize, (int)smem1);
    cudaFuncSetAttribute(fuse_kernel,
                         cudaFuncAttributeMaxDynamicSharedMemorySize, (int)smem2);

    img_gemm_kernel<<<dim3(HW/128, BATCH), 256, smem1>>>(
        img, w_it, b_it, g_itp, be_it, m_it, v_it);

    fuse_kernel<<<NVOX/128, 512, smem2>>>(
        vf, coords, boxes, classes,
        w_vt, b_vt, g_vt, be_vt, m_vt, v_vt,
        w_f, b_f, g_f, be_f, m_f, v_f,
        out);
}

// round 9
// speedup vs baseline: 1.0748x; 1.0748x over previous
#include <cuda_runtime.h>
#include <cuda_bf16.h>
#include <cstdint>

// Problem constants
#define NVOX   262144
#define BATCH  4
#define NBOX   32
#define C3D    64
#define C2D    256
#define MIDC   128
#define OUTC   64
#define IMH    96
#define IMW    312
#define HW     (IMH*IMW)        // 29952

// Intermediate image features, NHWC: [b][pix][mid], 61.3 MB
__device__ __align__(256) float g_itbuf[(size_t)BATCH * HW * MIDC];

// ---------------------------------------------------------------------------
// tf32 warp MMA helpers (sm_80+ PTX; compiles for compute_103)
// ---------------------------------------------------------------------------
__device__ __forceinline__ float to_tf32(float x) {
    float r;
    asm("cvt.rna.tf32.f32 %0, %1;" : "=f"(r) : "f"(x));
    return r;
}
__device__ __forceinline__ void mma8(float* d,
                                     uint32_t a0, uint32_t a1, uint32_t a2, uint32_t a3,
                                     uint32_t b0, uint32_t b1) {
    asm volatile("mma.sync.aligned.m16n8k8.row.col.f32.tf32.tf32.f32 "
                 "{%0,%1,%2,%3}, {%4,%5,%6,%7}, {%8,%9}, {%0,%1,%2,%3};"
                 : "+f"(d[0]), "+f"(d[1]), "+f"(d[2]), "+f"(d[3])
                 : "r"(a0), "r"(a1), "r"(a2), "r"(a3), "r"(b0), "r"(b1));
}

// ---------------------------------------------------------------------------
// Kernel 1: it = relu(bn(conv1x1(image)))  -> g_itbuf (NHWC)  [unchanged, proven]
// ---------------------------------------------------------------------------
__global__ __launch_bounds__(256) void img_gemm_kernel(
    const float* __restrict__ img,
    const float* __restrict__ w_it,
    const float* __restrict__ b_it,
    const float* __restrict__ gam,
    const float* __restrict__ bet,
    const float* __restrict__ mu,
    const float* __restrict__ var)
{
    extern __shared__ float sm1[];
    float* sImg = sm1;
    float* sW   = sm1 + 64*128;
    float* sS   = sm1 + 2*64*128;
    float* sO   = sS + 128;

    const int tid = threadIdx.x;
    const int b   = blockIdx.y;
    const int hw0 = blockIdx.x * 128;

    if (tid < 128) {
        float s = gam[tid] * rsqrtf(var[tid] + 1e-5f);
        sS[tid] = s;
        sO[tid] = (b_it[tid] - mu[tid]) * s + bet[tid];
    }

    const int rowg = (tid >> 4) * 8;
    const int colg = (tid & 15) * 8;
    float acc[8][8];
    #pragma unroll
    for (int i = 0; i < 8; i++)
        #pragma unroll
        for (int j = 0; j < 8; j++) acc[i][j] = 0.f;

    for (int kc = 0; kc < C2D; kc += 64) {
        __syncthreads();
        #pragma unroll
        for (int i = 0; i < 8; i++) {
            int idx = tid + i*256;
            int kk = idx >> 5, c4 = (idx & 31) << 2;
            float4 f = *(const float4*)&img[(size_t)((b*C2D + kc + kk))*HW + hw0 + c4];
            *(float4*)&sImg[kk*128 + c4] = f;
        }
        #pragma unroll
        for (int i = 0; i < 8; i++) {
            int idx = tid + i*256;
            int mid = idx & 127, kq = idx >> 7;
            float4 f = *(const float4*)&w_it[mid*C2D + kc + kq*4];
            sW[(kq*4+0)*128 + mid] = f.x;
            sW[(kq*4+1)*128 + mid] = f.y;
            sW[(kq*4+2)*128 + mid] = f.z;
            sW[(kq*4+3)*128 + mid] = f.w;
        }
        __syncthreads();
        #pragma unroll 16
        for (int kk = 0; kk < 64; kk++) {
            float a[8], bb[8];
            *(float4*)(a)    = *(const float4*)&sImg[kk*128 + rowg];
            *(float4*)(a+4)  = *(const float4*)&sImg[kk*128 + rowg + 4];
            *(float4*)(bb)   = *(const float4*)&sW[kk*128 + colg];
            *(float4*)(bb+4) = *(const float4*)&sW[kk*128 + colg + 4];
            #pragma unroll
            for (int i = 0; i < 8; i++)
                #pragma unroll
                for (int j = 0; j < 8; j++)
                    acc[i][j] = fmaf(a[i], bb[j], acc[i][j]);
        }
    }
    #pragma unroll
    for (int i = 0; i < 8; i++) {
        size_t base = ((size_t)b*HW + hw0 + rowg + i) * MIDC + colg;
        float4 o0, o1;
        o0.x = fmaxf(fmaf(acc[i][0], sS[colg+0], sO[colg+0]), 0.f);
        o0.y = fmaxf(fmaf(acc[i][1], sS[colg+1], sO[colg+1]), 0.f);
        o0.z = fmaxf(fmaf(acc[i][2], sS[colg+2], sO[colg+2]), 0.f);
        o0.w = fmaxf(fmaf(acc[i][3], sS[colg+3], sO[colg+3]), 0.f);
        o1.x = fmaxf(fmaf(acc[i][4], sS[colg+4], sO[colg+4]), 0.f);
        o1.y = fmaxf(fmaf(acc[i][5], sS[colg+5], sO[colg+5]), 0.f);
        o1.z = fmaxf(fmaf(acc[i][6], sS[colg+6], sO[colg+6]), 0.f);
        o1.w = fmaxf(fmaf(acc[i][7], sS[colg+7], sO[colg+7]), 0.f);
        *(float4*)&g_itbuf[base]     = o0;
        *(float4*)&g_itbuf[base + 4] = o1;
    }
}

// ---------------------------------------------------------------------------
// Kernel 2: fused pipeline, both GEMMs on mma.sync tf32.
// SMEM float map:
//   [0,     34816)  fusedT [256 ch][136]  (stage-2 A operand, k-major)
//   [34816, 53248)  region2, aliased in time:
//      stage1:  vfT [64][136] @34816, wvtT [64][136] @43520
//      stage2:  wfT [256 k][72] @34816
//      epi2:    outT [128][68] @34816
//   [53248, 55808)  consts
// Total 223,232 B dynamic smem.
// ---------------------------------------------------------------------------
#define FP     136              // fusedT / vfT / wvtT pitch (mod 32 == 8)
#define WFP    72               // wfT pitch (mod 32 == 8)
#define OTP    68               // outT pitch (multiple of 4)
#define SM2_BYTES (55808*4)

__global__ __launch_bounds__(512) void fuse_kernel(
    const float* __restrict__ vf,
    const int*   __restrict__ coords,
    const float* __restrict__ gt_boxes,
    const int*   __restrict__ gt_classes,
    const float* __restrict__ w_vt,
    const float* __restrict__ b_vt,
    const float* __restrict__ g_vt,
    const float* __restrict__ be_vt,
    const float* __restrict__ m_vt,
    const float* __restrict__ v_vt,
    const float* __restrict__ w_f,
    const float* __restrict__ b_f,
    const float* __restrict__ g_f,
    const float* __restrict__ be_f,
    const float* __restrict__ m_f,
    const float* __restrict__ v_f,
    float* __restrict__ out)
{
    extern __shared__ float sm[];
    float* fusedT  = sm;                  // [256][FP]
    float* vfT     = sm + 34816;          // [64][FP]
    float* wvtT    = sm + 43520;          // [64][FP]
    float* wfT     = sm + 34816;          // [256][WFP]  (alias, after stage 1)
    float* outT    = sm + 34816;          // [128][OTP]  (alias, after stage 2)
    float* boxes_s = sm + 53248;          // 896
    float* sA      = boxes_s + 896;       // 128
    float* oA      = sA + 128;            // 128
    float* sF      = oA + 128;            // 64
    float* oF      = sF + 64;             // 64
    float* w3d_s   = oF + 64;             // 128
    float* cw_s    = w3d_s + 128;         // 512
    int*   cls_s   = (int*)(cw_s + 512);  // 128
    int*   coff_s  = cls_s + 128;         // 512

    const int tid = threadIdx.x;
    const int wid = tid >> 5;
    const int lid = tid & 31;
    const int q   = lid & 3;     // threadID_in_group
    const int p   = lid >> 2;    // groupID
    const int v0  = blockIdx.x * 128;

    // ---- stage 0 loads ----
    for (int i = tid; i < 896; i += 512) boxes_s[i] = gt_boxes[i];
    if (tid < 128) {
        cls_s[tid] = gt_classes[tid];
        float s = g_vt[tid] * rsqrtf(v_vt[tid] + 1e-5f);
        sA[tid] = s;
        oA[tid] = (b_vt[tid] - m_vt[tid]) * s + be_vt[tid];
    } else if (tid < 192) {
        int c = tid - 128;
        float s = g_f[c] * rsqrtf(v_f[c] + 1e-5f);
        sF[c] = s;
        oF[c] = (b_f[c] - m_f[c]) * s + be_f[c];
    }
    // vfT[k][row] (tf32), pitch FP
    #pragma unroll
    for (int i = 0; i < 4; i++) {
        int idx = tid + i*512;
        int r = idx >> 4, k4 = (idx & 15) << 2;
        float4 f = *(const float4*)&vf[(size_t)(v0 + r)*C3D + k4];
        vfT[(k4+0)*FP + r] = to_tf32(f.x);
        vfT[(k4+1)*FP + r] = to_tf32(f.y);
        vfT[(k4+2)*FP + r] = to_tf32(f.z);
        vfT[(k4+3)*FP + r] = to_tf32(f.w);
    }
    // wvtT[k][mid] (tf32), pitch FP
    #pragma unroll
    for (int i = 0; i < 4; i++) {
        int idx = tid + i*512;
        int mid = idx & 127, kq = idx >> 7;
        float4 f = *(const float4*)&w_vt[mid*C3D + kq*4];
        wvtT[(kq*4+0)*FP + mid] = to_tf32(f.x);
        wvtT[(kq*4+1)*FP + mid] = to_tf32(f.y);
        wvtT[(kq*4+2)*FP + mid] = to_tf32(f.z);
        wvtT[(kq*4+3)*FP + mid] = to_tf32(f.w);
    }
    __syncthreads();

    // ---- stage 0b: per-voxel scalar work ----
    if (tid < 128) {
        int4 c = *(const int4*)&coords[(size_t)(v0 + tid)*4];
        int b = c.x;
        float crx = (float)c.w * 0.05f;
        float cry = (float)c.z * 0.05f - 40.f;
        float crz = (float)c.y * 0.1f  - 3.f;
        int last = -1;
        const float* bb = boxes_s + b*224;
        #pragma unroll
        for (int mi = 0; mi < NBOX; mi++) {
            const float* pb = bb + mi*7;
            bool in = (fabsf(crx - pb[0]) < pb[3]*0.5f) &&
                      (fabsf(cry - pb[1]) < pb[4]*0.5f) &&
                      (fabsf(crz - pb[2]) < pb[5]*0.5f) &&
                      (pb[3] > 0.f);
            if (in) last = mi;
        }
        float w3;
        if (last >= 0) {
            int cl = cls_s[b*NBOX + last];
            w3 = (cl == 0) ? 0.85f : ((cl == 1) ? 0.95f : 0.6f);
        } else w3 = 0.8f;
        w3d_s[tid] = w3;
        float cx = crx + 0.025f;
        float cy = cry + 0.025f;
        float px = cx*10.f + (float)IMW*0.5f;
        float py = cy*10.f + (float)IMH*0.5f;
        float nx = fminf(fmaxf(px/(float)IMW*2.f - 1.f, -1.f), 1.f);
        float ny = fminf(fmaxf(py/(float)IMH*2.f - 1.f, -1.f), 1.f);
        float fx = ((nx + 1.f)*(float)IMW - 1.f)*0.5f;
        float fy = ((ny + 1.f)*(float)IMH - 1.f)*0.5f;
        float x0f = floorf(fx), y0f = floorf(fy);
        float wx = fx - x0f, wy = fy - y0f;
        int x0 = (int)x0f, y0 = (int)y0f;
        #pragma unroll
        for (int ci = 0; ci < 4; ci++) {
            int dx = ci & 1, dy = ci >> 1;
            int xi = x0 + dx, yi = y0 + dy;
            bool val = (xi >= 0) && (xi < IMW) && (yi >= 0) && (yi < IMH);
            int xc = min(max(xi, 0), IMW-1);
            int yc = min(max(yi, 0), IMH-1);
            float wgt = (dx ? wx : 1.f - wx) * (dy ? wy : 1.f - wy);
            cw_s[tid*4 + ci]   = val ? wgt : 0.f;
            coff_s[tid*4 + ci] = ((b*IMH + yc)*IMW + xc) * MIDC;
        }
    }

    // ---- stage 1: vt GEMM via mma.sync tf32 (M128 N128 K64) ----
    // warp w: rows m0..m0+15, cols nb..nb+63 (8 n-tiles of 8)
    const int m0 = (wid >> 1) * 16;
    const int nb = (wid & 1) * 64;
    float d1[8][4];
    #pragma unroll
    for (int t = 0; t < 8; t++)
        #pragma unroll
        for (int j = 0; j < 4; j++) d1[t][j] = 0.f;
    {
        const uint32_t* A = (const uint32_t*)vfT;
        const uint32_t* B = (const uint32_t*)wvtT;
        #pragma unroll
        for (int kc = 0; kc < 8; kc++) {
            int k0 = kc * 8;
            uint32_t a0 = A[(k0+q)*FP   + m0 + p];
            uint32_t a1 = A[(k0+q)*FP   + m0 + 8 + p];
            uint32_t a2 = A[(k0+4+q)*FP + m0 + p];
            uint32_t a3 = A[(k0+4+q)*FP + m0 + 8 + p];
            #pragma unroll
            for (int t = 0; t < 8; t++) {
                int n0 = nb + t*8;
                uint32_t b0 = B[(k0+q)*FP   + n0 + p];
                uint32_t b1 = B[(k0+4+q)*FP + n0 + p];
                mma8(d1[t], a0, a1, a2, a3, b0, b1);
            }
        }
    }
    __syncthreads();   // vfT/wvtT dead; w3d/cw/coff visible to all

    // ---- load w_f -> wfT[k][o] tf32, pitch WFP (aliases vfT/wvtT) ----
    #pragma unroll
    for (int i = 0; i < 8; i++) {
        int idx4 = tid + i*512;          // 4096 float4s
        int o  = idx4 >> 6;              // 0..63
        int kq = (idx4 & 63) << 2;       // 0..252
        float4 f = *(const float4*)&w_f[o*256 + kq];
        wfT[(kq+0)*WFP + o] = to_tf32(f.x);
        wfT[(kq+1)*WFP + o] = to_tf32(f.y);
        wfT[(kq+2)*WFP + o] = to_tf32(f.z);
        wfT[(kq+3)*WFP + o] = to_tf32(f.w);
    }

    // ---- stage 1 epilogue: bn+relu, * w3d -> fusedT (ch 0..127, k-major) ----
    #pragma unroll
    for (int t = 0; t < 8; t++) {
        int n0 = nb + t*8;
        int c0 = n0 + 2*q, c1 = c0 + 1;
        int r0 = m0 + p,   r1 = r0 + 8;
        float w30 = w3d_s[r0], w31 = w3d_s[r1];
        fusedT[c0*FP + r0] = to_tf32(fmaxf(fmaf(d1[t][0], sA[c0], oA[c0]), 0.f) * w30);
        fusedT[c1*FP + r0] = to_tf32(fmaxf(fmaf(d1[t][1], sA[c1], oA[c1]), 0.f) * w30);
        fusedT[c0*FP + r1] = to_tf32(fmaxf(fmaf(d1[t][2], sA[c0], oA[c0]), 0.f) * w31);
        fusedT[c1*FP + r1] = to_tf32(fmaxf(fmaf(d1[t][3], sA[c1], oA[c1]), 0.f) * w31);
    }

    // ---- stage 1b: bilinear sampling -> fusedT (ch 128..255) ----
    {
        int v  = tid & 127;
        int cb = (tid >> 7) * 32;
        float wim = 1.f - w3d_s[v];
        float4 acc4[8];
        #pragma unroll
        for (int j = 0; j < 8; j++) acc4[j] = make_float4(0.f, 0.f, 0.f, 0.f);
        #pragma unroll
        for (int ci = 0; ci < 4; ci++) {
            float wgt = cw_s[v*4 + ci] * wim;
            const float4* pp = (const float4*)&g_itbuf[(size_t)coff_s[v*4 + ci] + cb];
            #pragma unroll
            for (int j = 0; j < 8; j++) {
                float4 f = pp[j];
                acc4[j].x = fmaf(wgt, f.x, acc4[j].x);
                acc4[j].y = fmaf(wgt, f.y, acc4[j].y);
                acc4[j].z = fmaf(wgt, f.z, acc4[j].z);
                acc4[j].w = fmaf(wgt, f.w, acc4[j].w);
            }
        }
        #pragma unroll
        for (int j = 0; j < 8; j++) {
            int ch = 128 + cb + j*4;
            fusedT[(ch+0)*FP + v] = to_tf32(acc4[j].x);
            fusedT[(ch+1)*FP + v] = to_tf32(acc4[j].y);
            fusedT[(ch+2)*FP + v] = to_tf32(acc4[j].z);
            fusedT[(ch+3)*FP + v] = to_tf32(acc4[j].w);
        }
    }
    __syncthreads();

    // ---- stage 2: final GEMM via mma.sync tf32 (M128 N64 K256) ----
    // warp w: rows m0b..m0b+15, cols nbb..nbb+31 (4 n-tiles of 8)
    const int m0b = (wid & 7) * 16;
    const int nbb = (wid >> 3) * 32;
    float d2[4][4];
    #pragma unroll
    for (int t = 0; t < 4; t++)
        #pragma unroll
        for (int j = 0; j < 4; j++) d2[t][j] = 0.f;
    {
        const uint32_t* A = (const uint32_t*)fusedT;
        const uint32_t* B = (const uint32_t*)wfT;
        #pragma unroll 4
        for (int kc = 0; kc < 32; kc++) {
            int k0 = kc * 8;
            uint32_t a0 = A[(k0+q)*FP   + m0b + p];
            uint32_t a1 = A[(k0+q)*FP   + m0b + 8 + p];
            uint32_t a2 = A[(k0+4+q)*FP + m0b + p];
            uint32_t a3 = A[(k0+4+q)*FP + m0b + 8 + p];
            #pragma unroll
            for (int t = 0; t < 4; t++) {
                int n0 = nbb + t*8;
                uint32_t b0 = B[(k0+q)*WFP   + n0 + p];
                uint32_t b1 = B[(k0+4+q)*WFP + n0 + p];
                mma8(d2[t], a0, a1, a2, a3, b0, b1);
            }
        }
    }
    __syncthreads();   // wfT dead -> outT may overwrite

    // ---- epilogue 2a: bn+relu -> outT (row-major, pitch OTP) ----
    #pragma unroll
    for (int t = 0; t < 4; t++) {
        int n0 = nbb + t*8;
        int c0 = n0 + 2*q, c1 = c0 + 1;
        int r0 = m0b + p,  r1 = r0 + 8;
        outT[r0*OTP + c0] = fmaxf(fmaf(d2[t][0], sF[c0], oF[c0]), 0.f);
        outT[r0*OTP + c1] = fmaxf(fmaf(d2[t][1], sF[c1], oF[c1]), 0.f);
        outT[r1*OTP + c0] = fmaxf(fmaf(d2[t][2], sF[c0], oF[c0]), 0.f);
        outT[r1*OTP + c1] = fmaxf(fmaf(d2[t][3], sF[c1], oF[c1]), 0.f);
    }
    __syncthreads();

    // ---- epilogue 2b: coalesced float4 store to out ----
    #pragma unroll
    for (int i = 0; i < 4; i++) {
        int idx4 = tid + i*512;          // 2048 float4s
        int r = idx4 >> 4, c = (idx4 & 15) << 2;
        float4 f = *(const float4*)&outT[r*OTP + c];
        *(float4*)&out[(size_t)(v0 + r)*OUTC + c] = f;
    }
}

// ---------------------------------------------------------------------------
extern "C" void kernel_launch(void* const* d_in, const int* in_sizes, int n_in,
                              void* d_out, int out_size)
{
    const float* vf       = (const float*)d_in[0];
    const int*   coords   = (const int*)  d_in[1];
    const float* img      = (const float*)d_in[2];
    const float* boxes    = (const float*)d_in[3];
    const int*   classes  = (const int*)  d_in[4];
    const float* w_vt     = (const float*)d_in[5];
    const float* b_vt     = (const float*)d_in[6];
    const float* g_vt     = (const float*)d_in[7];
    const float* be_vt    = (const float*)d_in[8];
    const float* m_vt     = (const float*)d_in[9];
    const float* v_vt     = (const float*)d_in[10];
    const float* w_it     = (const float*)d_in[11];
    const float* b_it     = (const float*)d_in[12];
    const float* g_itp    = (const float*)d_in[13];
    const float* be_it    = (const float*)d_in[14];
    const float* m_it     = (const float*)d_in[15];
    const float* v_it     = (const float*)d_in[16];
    const float* w_f      = (const float*)d_in[17];
    const float* b_f      = (const float*)d_in[18];
    const float* g_f      = (const float*)d_in[19];
    const float* be_f     = (const float*)d_in[20];
    const float* m_f      = (const float*)d_in[21];
    const float* v_f      = (const float*)d_in[22];
    float* out = (float*)d_out;

    const size_t smem1 = (size_t)(2*64*128 + 256) * sizeof(float);     // 66,560 B
    cudaFuncSetAttribute(img_gemm_kernel,
                         cudaFuncAttributeMaxDynamicSharedMemorySize, (int)smem1);
    cudaFuncSetAttribute(fuse_kernel,
                         cudaFuncAttributeMaxDynamicSharedMemorySize, SM2_BYTES);

    img_gemm_kernel<<<dim3(HW/128, BATCH), 256, smem1>>>(
        img, w_it, b_it, g_itp, be_it, m_it, v_it);

    fuse_kernel<<<NVOX/128, 512, SM2_BYTES>>>(
        vf, coords, boxes, classes,
        w_vt, b_vt, g_vt, be_vt, m_vt, v_vt,
        w_f, b_f, g_f, be_f, m_f, v_f,
        out);
}

// round 11
// speedup vs baseline: 1.2520x; 1.1648x over previous
#include <cuda_runtime.h>
#include <cuda_bf16.h>
#include <cstdint>

// Problem constants
#define NVOX   262144
#define BATCH  4
#define NBOX   32
#define C3D    64
#define C2D    256
#define MIDC   128
#define OUTC   64
#define IMH    96
#define IMW    312
#define HW     (IMH*IMW)        // 29952

// Intermediate image features, NHWC: [b][pix][mid], 61.3 MB
__device__ __align__(256) float g_itbuf[(size_t)BATCH * HW * MIDC];

// ---------------------------------------------------------------------------
// tf32 warp MMA helpers (sm_80+ PTX; compiles for compute_103)  [VALIDATED]
// ---------------------------------------------------------------------------
__device__ __forceinline__ float to_tf32(float x) {
    float r;
    asm("cvt.rna.tf32.f32 %0, %1;" : "=f"(r) : "f"(x));
    return r;
}
__device__ __forceinline__ void mma8(float* d,
                                     uint32_t a0, uint32_t a1, uint32_t a2, uint32_t a3,
                                     uint32_t b0, uint32_t b1) {
    asm volatile("mma.sync.aligned.m16n8k8.row.col.f32.tf32.tf32.f32 "
                 "{%0,%1,%2,%3}, {%4,%5,%6,%7}, {%8,%9}, {%0,%1,%2,%3};"
                 : "+f"(d[0]), "+f"(d[1]), "+f"(d[2]), "+f"(d[3])
                 : "r"(a0), "r"(a1), "r"(a2), "r"(a3), "r"(b0), "r"(b1));
}

// ---------------------------------------------------------------------------
// Kernel 1: it = relu(bn(conv1x1(image)))  -> g_itbuf (NHWC)
// tf32 mma.sync: M=128 pix x N=128 mid x K=256, 4 k-chunks of 64.
// SMEM floats: sImg [64][136] @0, sW [64][136] @8704, sS @17408, sO @17536.
// outS [128][132] aliases [0,16896) after last MMA.  Total 70,656 B.
// ---------------------------------------------------------------------------
#define IP    136     // sImg/sW pitch (mod 32 == 8 -> conflict-free frags)
#define OSP   132     // outS pitch
#define SM1_FLOATS (2*64*IP + 256)

__global__ __launch_bounds__(256) void img_gemm_kernel(
    const float* __restrict__ img,
    const float* __restrict__ w_it,
    const float* __restrict__ b_it,
    const float* __restrict__ gam,
    const float* __restrict__ bet,
    const float* __restrict__ mu,
    const float* __restrict__ var)
{
    extern __shared__ float sm1[];
    float* sImg = sm1;                 // [64][IP]
    float* sW   = sm1 + 64*IP;         // [64][IP]
    float* sS   = sm1 + 2*64*IP;       // [128]
    float* sO   = sS + 128;            // [128]
    float* outS = sm1;                 // [128][OSP] alias (after last MMA)

    const int tid = threadIdx.x;
    const int wid = tid >> 5;
    const int lid = tid & 31;
    const int q   = lid & 3;
    const int p   = lid >> 2;
    const int b   = blockIdx.y;
    const int hw0 = blockIdx.x * 128;

    if (tid < 128) {
        float s = gam[tid] * rsqrtf(var[tid] + 1e-5f);
        sS[tid] = s;
        sO[tid] = (b_it[tid] - mu[tid]) * s + bet[tid];
    }

    // warp w: rows 16w..16w+15 (pixels), all 128 mids = 16 n-tiles
    const int m0 = wid * 16;
    float d[16][4];
    #pragma unroll
    for (int t = 0; t < 16; t++)
        #pragma unroll
        for (int j = 0; j < 4; j++) d[t][j] = 0.f;

    for (int kc = 0; kc < C2D; kc += 64) {
        __syncthreads();
        // fill sImg [64 k][128 pix] (tf32), coalesced
        #pragma unroll
        for (int i = 0; i < 8; i++) {
            int idx = tid + i*256;
            int kk = idx >> 5, c4 = (idx & 31) << 2;
            float4 f = *(const float4*)&img[(size_t)((b*C2D + kc + kk))*HW + hw0 + c4];
            float* dst = &sImg[kk*IP + c4];
            dst[0] = to_tf32(f.x); dst[1] = to_tf32(f.y);
            dst[2] = to_tf32(f.z); dst[3] = to_tf32(f.w);
        }
        // fill sW [64 k][128 mid] (tf32), transposed scatter (conflict-free)
        #pragma unroll
        for (int i = 0; i < 8; i++) {
            int idx = tid + i*256;
            int mid = idx & 127, kq = idx >> 7;
            float4 f = *(const float4*)&w_it[mid*C2D + kc + kq*4];
            sW[(kq*4+0)*IP + mid] = to_tf32(f.x);
            sW[(kq*4+1)*IP + mid] = to_tf32(f.y);
            sW[(kq*4+2)*IP + mid] = to_tf32(f.z);
            sW[(kq*4+3)*IP + mid] = to_tf32(f.w);
        }
        __syncthreads();
        // MMA over this 64-k chunk
        const uint32_t* A = (const uint32_t*)sImg;
        const uint32_t* B = (const uint32_t*)sW;
        #pragma unroll
        for (int kc8 = 0; kc8 < 8; kc8++) {
            int k0 = kc8 * 8;
            uint32_t a0 = A[(k0+q)*IP   + m0 + p];
            uint32_t a1 = A[(k0+q)*IP   + m0 + 8 + p];
            uint32_t a2 = A[(k0+4+q)*IP + m0 + p];
            uint32_t a3 = A[(k0+4+q)*IP + m0 + 8 + p];
            #pragma unroll
            for (int t = 0; t < 16; t++) {
                int n0 = t*8;
                uint32_t b0 = B[(k0+q)*IP   + n0 + p];
                uint32_t b1 = B[(k0+4+q)*IP + n0 + p];
                mma8(d[t], a0, a1, a2, a3, b0, b1);
            }
        }
    }
    __syncthreads();   // last MMA done -> outS may overwrite sImg/sW

    // epilogue: bn + relu -> outS
    #pragma unroll
    for (int t = 0; t < 16; t++) {
        int n0 = t*8;
        int c0 = n0 + 2*q, c1 = c0 + 1;
        int r0 = m0 + p,   r1 = r0 + 8;
        outS[r0*OSP + c0] = fmaxf(fmaf(d[t][0], sS[c0], sO[c0]), 0.f);
        outS[r0*OSP + c1] = fmaxf(fmaf(d[t][1], sS[c1], sO[c1]), 0.f);
        outS[r1*OSP + c0] = fmaxf(fmaf(d[t][2], sS[c0], sO[c0]), 0.f);
        outS[r1*OSP + c1] = fmaxf(fmaf(d[t][3], sS[c1], sO[c1]), 0.f);
    }
    __syncthreads();

    // coalesced float4 store to g_itbuf (NHWC)
    #pragma unroll
    for (int i = 0; i < 16; i++) {
        int idx = tid + i*256;           // 4096 float4s
        int r = idx >> 5, c4 = (idx & 31) << 2;
        float4 f = *(const float4*)&outS[r*OSP + c4];
        *(float4*)&g_itbuf[((size_t)b*HW + hw0 + r)*MIDC + c4] = f;
    }
}

// ---------------------------------------------------------------------------
// Kernel 2: fused pipeline, both GEMMs on mma.sync tf32.  [UNCHANGED, passing]
// ---------------------------------------------------------------------------
#define FP     136              // fusedT / vfT / wvtT pitch (mod 32 == 8)
#define WFP    72               // wfT pitch (mod 32 == 8)
#define OTP    68               // outT pitch (multiple of 4)
#define SM2_BYTES (55808*4)

__global__ __launch_bounds__(512) void fuse_kernel(
    const float* __restrict__ vf,
    const int*   __restrict__ coords,
    const float* __restrict__ gt_boxes,
    const int*   __restrict__ gt_classes,
    const float* __restrict__ w_vt,
    const float* __restrict__ b_vt,
    const float* __restrict__ g_vt,
    const float* __restrict__ be_vt,
    const float* __restrict__ m_vt,
    const float* __restrict__ v_vt,
    const float* __restrict__ w_f,
    const float* __restrict__ b_f,
    const float* __restrict__ g_f,
    const float* __restrict__ be_f,
    const float* __restrict__ m_f,
    const float* __restrict__ v_f,
    float* __restrict__ out)
{
    extern __shared__ float sm[];
    float* fusedT  = sm;                  // [256][FP]
    float* vfT     = sm + 34816;          // [64][FP]
    float* wvtT    = sm + 43520;          // [64][FP]
    float* wfT     = sm + 34816;          // [256][WFP]  (alias, after stage 1)
    float* outT    = sm + 34816;          // [128][OTP]  (alias, after stage 2)
    float* boxes_s = sm + 53248;          // 896
    float* sA      = boxes_s + 896;       // 128
    float* oA      = sA + 128;            // 128
    float* sF      = oA + 128;            // 64
    float* oF      = sF + 64;             // 64
    float* w3d_s   = oF + 64;             // 128
    float* cw_s    = w3d_s + 128;         // 512
    int*   cls_s   = (int*)(cw_s + 512);  // 128
    int*   coff_s  = cls_s + 128;         // 512

    const int tid = threadIdx.x;
    const int wid = tid >> 5;
    const int lid = tid & 31;
    const int q   = lid & 3;     // threadID_in_group
    const int p   = lid >> 2;    // groupID
    const int v0  = blockIdx.x * 128;

    // ---- stage 0 loads ----
    for (int i = tid; i < 896; i += 512) boxes_s[i] = gt_boxes[i];
    if (tid < 128) {
        cls_s[tid] = gt_classes[tid];
        float s = g_vt[tid] * rsqrtf(v_vt[tid] + 1e-5f);
        sA[tid] = s;
        oA[tid] = (b_vt[tid] - m_vt[tid]) * s + be_vt[tid];
    } else if (tid < 192) {
        int c = tid - 128;
        float s = g_f[c] * rsqrtf(v_f[c] + 1e-5f);
        sF[c] = s;
        oF[c] = (b_f[c] - m_f[c]) * s + be_f[c];
    }
    // vfT[k][row] (tf32), pitch FP
    #pragma unroll
    for (int i = 0; i < 4; i++) {
        int idx = tid + i*512;
        int r = idx >> 4, k4 = (idx & 15) << 2;
        float4 f = *(const float4*)&vf[(size_t)(v0 + r)*C3D + k4];
        vfT[(k4+0)*FP + r] = to_tf32(f.x);
        vfT[(k4+1)*FP + r] = to_tf32(f.y);
        vfT[(k4+2)*FP + r] = to_tf32(f.z);
        vfT[(k4+3)*FP + r] = to_tf32(f.w);
    }
    // wvtT[k][mid] (tf32), pitch FP
    #pragma unroll
    for (int i = 0; i < 4; i++) {
        int idx = tid + i*512;
        int mid = idx & 127, kq = idx >> 7;
        float4 f = *(const float4*)&w_vt[mid*C3D + kq*4];
        wvtT[(kq*4+0)*FP + mid] = to_tf32(f.x);
        wvtT[(kq*4+1)*FP + mid] = to_tf32(f.y);
        wvtT[(kq*4+2)*FP + mid] = to_tf32(f.z);
        wvtT[(kq*4+3)*FP + mid] = to_tf32(f.w);
    }
    __syncthreads();

    // ---- stage 0b: per-voxel scalar work ----
    if (tid < 128) {
        int4 c = *(const int4*)&coords[(size_t)(v0 + tid)*4];
        int b = c.x;
        float crx = (float)c.w * 0.05f;
        float cry = (float)c.z * 0.05f - 40.f;
        float crz = (float)c.y * 0.1f  - 3.f;
        int last = -1;
        const float* bb = boxes_s + b*224;
        #pragma unroll
        for (int mi = 0; mi < NBOX; mi++) {
            const float* pb = bb + mi*7;
            bool in = (fabsf(crx - pb[0]) < pb[3]*0.5f) &&
                      (fabsf(cry - pb[1]) < pb[4]*0.5f) &&
                      (fabsf(crz - pb[2]) < pb[5]*0.5f) &&
                      (pb[3] > 0.f);
            if (in) last = mi;
        }
        float w3;
        if (last >= 0) {
            int cl = cls_s[b*NBOX + last];
            w3 = (cl == 0) ? 0.85f : ((cl == 1) ? 0.95f : 0.6f);
        } else w3 = 0.8f;
        w3d_s[tid] = w3;
        float cx = crx + 0.025f;
        float cy = cry + 0.025f;
        float px = cx*10.f + (float)IMW*0.5f;
        float py = cy*10.f + (float)IMH*0.5f;
        float nx = fminf(fmaxf(px/(float)IMW*2.f - 1.f, -1.f), 1.f);
        float ny = fminf(fmaxf(py/(float)IMH*2.f - 1.f, -1.f), 1.f);
        float fx = ((nx + 1.f)*(float)IMW - 1.f)*0.5f;
        float fy = ((ny + 1.f)*(float)IMH - 1.f)*0.5f;
        float x0f = floorf(fx), y0f = floorf(fy);
        float wx = fx - x0f, wy = fy - y0f;
        int x0 = (int)x0f, y0 = (int)y0f;
        #pragma unroll
        for (int ci = 0; ci < 4; ci++) {
            int dx = ci & 1, dy = ci >> 1;
            int xi = x0 + dx, yi = y0 + dy;
            bool val = (xi >= 0) && (xi < IMW) && (yi >= 0) && (yi < IMH);
            int xc = min(max(xi, 0), IMW-1);
            int yc = min(max(yi, 0), IMH-1);
            float wgt = (dx ? wx : 1.f - wx) * (dy ? wy : 1.f - wy);
            cw_s[tid*4 + ci]   = val ? wgt : 0.f;
            coff_s[tid*4 + ci] = ((b*IMH + yc)*IMW + xc) * MIDC;
        }
    }

    // ---- stage 1: vt GEMM via mma.sync tf32 (M128 N128 K64) ----
    const int m0 = (wid >> 1) * 16;
    const int nb = (wid & 1) * 64;
    float d1[8][4];
    #pragma unroll
    for (int t = 0; t < 8; t++)
        #pragma unroll
        for (int j = 0; j < 4; j++) d1[t][j] = 0.f;
    {
        const uint32_t* A = (const uint32_t*)vfT;
        const uint32_t* B = (const uint32_t*)wvtT;
        #pragma unroll
        for (int kc = 0; kc < 8; kc++) {
            int k0 = kc * 8;
            uint32_t a0 = A[(k0+q)*FP   + m0 + p];
            uint32_t a1 = A[(k0+q)*FP   + m0 + 8 + p];
            uint32_t a2 = A[(k0+4+q)*FP + m0 + p];
            uint32_t a3 = A[(k0+4+q)*FP + m0 + 8 + p];
            #pragma unroll
            for (int t = 0; t < 8; t++) {
                int n0 = nb + t*8;
                uint32_t b0 = B[(k0+q)*FP   + n0 + p];
                uint32_t b1 = B[(k0+4+q)*FP + n0 + p];
                mma8(d1[t], a0, a1, a2, a3, b0, b1);
            }
        }
    }
    __syncthreads();   // vfT/wvtT dead; w3d/cw/coff visible to all

    // ---- load w_f -> wfT[k][o] tf32, pitch WFP (aliases vfT/wvtT) ----
    #pragma unroll
    for (int i = 0; i < 8; i++) {
        int idx4 = tid + i*512;          // 4096 float4s
        int o  = idx4 >> 6;              // 0..63
        int kq = (idx4 & 63) << 2;       // 0..252
        float4 f = *(const float4*)&w_f[o*256 + kq];
        wfT[(kq+0)*WFP + o] = to_tf32(f.x);
        wfT[(kq+1)*WFP + o] = to_tf32(f.y);
        wfT[(kq+2)*WFP + o] = to_tf32(f.z);
        wfT[(kq+3)*WFP + o] = to_tf32(f.w);
    }

    // ---- stage 1 epilogue: bn+relu, * w3d -> fusedT (ch 0..127, k-major) ----
    #pragma unroll
    for (int t = 0; t < 8; t++) {
        int n0 = nb + t*8;
        int c0 = n0 + 2*q, c1 = c0 + 1;
        int r0 = m0 + p,   r1 = r0 + 8;
        float w30 = w3d_s[r0], w31 = w3d_s[r1];
        fusedT[c0*FP + r0] = to_tf32(fmaxf(fmaf(d1[t][0], sA[c0], oA[c0]), 0.f) * w30);
        fusedT[c1*FP + r0] = to_tf32(fmaxf(fmaf(d1[t][1], sA[c1], oA[c1]), 0.f) * w30);
        fusedT[c0*FP + r1] = to_tf32(fmaxf(fmaf(d1[t][2], sA[c0], oA[c0]), 0.f) * w31);
        fusedT[c1*FP + r1] = to_tf32(fmaxf(fmaf(d1[t][3], sA[c1], oA[c1]), 0.f) * w31);
    }

    // ---- stage 1b: bilinear sampling -> fusedT (ch 128..255) ----
    {
        int v  = tid & 127;
        int cb = (tid >> 7) * 32;
        float wim = 1.f - w3d_s[v];
        float4 acc4[8];
        #pragma unroll
        for (int j = 0; j < 8; j++) acc4[j] = make_float4(0.f, 0.f, 0.f, 0.f);
        #pragma unroll
        for (int ci = 0; ci < 4; ci++) {
            float wgt = cw_s[v*4 + ci] * wim;
            const float4* pp = (const float4*)&g_itbuf[(size_t)coff_s[v*4 + ci] + cb];
            #pragma unroll
            for (int j = 0; j < 8; j++) {
                float4 f = pp[j];
                acc4[j].x = fmaf(wgt, f.x, acc4[j].x);
                acc4[j].y = fmaf(wgt, f.y, acc4[j].y);
                acc4[j].z = fmaf(wgt, f.z, acc4[j].z);
                acc4[j].w = fmaf(wgt, f.w, acc4[j].w);
            }
        }
        #pragma unroll
        for (int j = 0; j < 8; j++) {
            int ch = 128 + cb + j*4;
            fusedT[(ch+0)*FP + v] = to_tf32(acc4[j].x);
            fusedT[(ch+1)*FP + v] = to_tf32(acc4[j].y);
            fusedT[(ch+2)*FP + v] = to_tf32(acc4[j].z);
            fusedT[(ch+3)*FP + v] = to_tf32(acc4[j].w);
        }
    }
    __syncthreads();

    // ---- stage 2: final GEMM via mma.sync tf32 (M128 N64 K256) ----
    const int m0b = (wid & 7) * 16;
    const int nbb = (wid >> 3) * 32;
    float d2[4][4];
    #pragma unroll
    for (int t = 0; t < 4; t++)
        #pragma unroll
        for (int j = 0; j < 4; j++) d2[t][j] = 0.f;
    {
        const uint32_t* A = (const uint32_t*)fusedT;
        const uint32_t* B = (const uint32_t*)wfT;
        #pragma unroll 4
        for (int kc = 0; kc < 32; kc++) {
            int k0 = kc * 8;
            uint32_t a0 = A[(k0+q)*FP   + m0b + p];
            uint32_t a1 = A[(k0+q)*FP   + m0b + 8 + p];
            uint32_t a2 = A[(k0+4+q)*FP + m0b + p];
            uint32_t a3 = A[(k0+4+q)*FP + m0b + 8 + p];
            #pragma unroll
            for (int t = 0; t < 4; t++) {
                int n0 = nbb + t*8;
                uint32_t b0 = B[(k0+q)*WFP   + n0 + p];
                uint32_t b1 = B[(k0+4+q)*WFP + n0 + p];
                mma8(d2[t], a0, a1, a2, a3, b0, b1);
            }
        }
    }
    __syncthreads();   // wfT dead -> outT may overwrite

    // ---- epilogue 2a: bn+relu -> outT (row-major, pitch OTP) ----
    #pragma unroll
    for (int t = 0; t < 4; t++) {
        int n0 = nbb + t*8;
        int c0 = n0 + 2*q, c1 = c0 + 1;
        int r0 = m0b + p,  r1 = r0 + 8;
        outT[r0*OTP + c0] = fmaxf(fmaf(d2[t][0], sF[c0], oF[c0]), 0.f);
        outT[r0*OTP + c1] = fmaxf(fmaf(d2[t][1], sF[c1], oF[c1]), 0.f);
        outT[r1*OTP + c0] = fmaxf(fmaf(d2[t][2], sF[c0], oF[c0]), 0.f);
        outT[r1*OTP + c1] = fmaxf(fmaf(d2[t][3], sF[c1], oF[c1]), 0.f);
    }
    __syncthreads();

    // ---- epilogue 2b: coalesced float4 store to out ----
    #pragma unroll
    for (int i = 0; i < 4; i++) {
        int idx4 = tid + i*512;          // 2048 float4s
        int r = idx4 >> 4, c = (idx4 & 15) << 2;
        float4 f = *(const float4*)&outT[r*OTP + c];
        *(float4*)&out[(size_t)(v0 + r)*OUTC + c] = f;
    }
}

// ---------------------------------------------------------------------------
extern "C" void kernel_launch(void* const* d_in, const int* in_sizes, int n_in,
                              void* d_out, int out_size)
{
    const float* vf       = (const float*)d_in[0];
    const int*   coords   = (const int*)  d_in[1];
    const float* img      = (const float*)d_in[2];
    const float* boxes    = (const float*)d_in[3];
    const int*   classes  = (const int*)  d_in[4];
    const float* w_vt     = (const float*)d_in[5];
    const float* b_vt     = (const float*)d_in[6];
    const float* g_vt     = (const float*)d_in[7];
    const float* be_vt    = (const float*)d_in[8];
    const float* m_vt     = (const float*)d_in[9];
    const float* v_vt     = (const float*)d_in[10];
    const float* w_it     = (const float*)d_in[11];
    const float* b_it     = (const float*)d_in[12];
    const float* g_itp    = (const float*)d_in[13];
    const float* be_it    = (const float*)d_in[14];
    const float* m_it     = (const float*)d_in[15];
    const float* v_it     = (const float*)d_in[16];
    const float* w_f      = (const float*)d_in[17];
    const float* b_f      = (const float*)d_in[18];
    const float* g_f      = (const float*)d_in[19];
    const float* be_f     = (const float*)d_in[20];
    const float* m_f      = (const float*)d_in[21];
    const float* v_f      = (const float*)d_in[22];
    float* out = (float*)d_out;

    const size_t smem1 = (size_t)SM1_FLOATS * sizeof(float);   // 70,656 B
    cudaFuncSetAttribute(img_gemm_kernel,
                         cudaFuncAttributeMaxDynamicSharedMemorySize, (int)smem1);
    cudaFuncSetAttribute(fuse_kernel,
                         cudaFuncAttributeMaxDynamicSharedMemorySize, SM2_BYTES);

    img_gemm_kernel<<<dim3(HW/128, BATCH), 256, smem1>>>(
        img, w_it, b_it, g_itp, be_it, m_it, v_it);

    fuse_kernel<<<NVOX/128, 512, SM2_BYTES>>>(
        vf, coords, boxes, classes,
        w_vt, b_vt, g_vt, be_vt, m_vt, v_vt,
        w_f, b_f, g_f, be_f, m_f, v_f,
        out);
}

// round 13
// speedup vs baseline: 1.4112x; 1.1272x over previous
#include <cuda_runtime.h>
#include <cuda_bf16.h>
#include <cstdint>

// Problem constants
#define NVOX   262144
#define BATCH  4
#define NBOX   32
#define C3D    64
#define C2D    256
#define MIDC   128
#define OUTC   64
#define IMH    96
#define IMW    312
#define HW     (IMH*IMW)        // 29952

// Intermediate image features, NHWC: [b][pix][mid], 61.3 MB
__device__ __align__(256) float g_itbuf[(size_t)BATCH * HW * MIDC];

// ---------------------------------------------------------------------------
// tf32 warp MMA helpers (sm_80+ PTX; compiles for compute_103)  [VALIDATED]
// ---------------------------------------------------------------------------
__device__ __forceinline__ float to_tf32(float x) {
    float r;
    asm("cvt.rna.tf32.f32 %0, %1;" : "=f"(r) : "f"(x));
    return r;
}
__device__ __forceinline__ void mma8(float* d,
                                     uint32_t a0, uint32_t a1, uint32_t a2, uint32_t a3,
                                     uint32_t b0, uint32_t b1) {
    asm volatile("mma.sync.aligned.m16n8k8.row.col.f32.tf32.tf32.f32 "
                 "{%0,%1,%2,%3}, {%4,%5,%6,%7}, {%8,%9}, {%0,%1,%2,%3};"
                 : "+f"(d[0]), "+f"(d[1]), "+f"(d[2]), "+f"(d[3])
                 : "r"(a0), "r"(a1), "r"(a2), "r"(a3), "r"(b0), "r"(b1));
}

// ---------------------------------------------------------------------------
// Kernel 1: it = relu(bn(conv1x1(image)))  -> g_itbuf (NHWC)  [VALIDATED tf32]
// ---------------------------------------------------------------------------
#define IP    136     // sImg/sW pitch (mod 32 == 8 -> conflict-free frags)
#define OSP   132     // outS pitch
#define SM1_FLOATS (2*64*IP + 256)

__global__ __launch_bounds__(256) void img_gemm_kernel(
    const float* __restrict__ img,
    const float* __restrict__ w_it,
    const float* __restrict__ b_it,
    const float* __restrict__ gam,
    const float* __restrict__ bet,
    const float* __restrict__ mu,
    const float* __restrict__ var)
{
    extern __shared__ float sm1[];
    float* sImg = sm1;                 // [64][IP]
    float* sW   = sm1 + 64*IP;         // [64][IP]
    float* sS   = sm1 + 2*64*IP;       // [128]
    float* sO   = sS + 128;            // [128]
    float* outS = sm1;                 // [128][OSP] alias (after last MMA)

    const int tid = threadIdx.x;
    const int wid = tid >> 5;
    const int lid = tid & 31;
    const int q   = lid & 3;
    const int p   = lid >> 2;
    const int b   = blockIdx.y;
    const int hw0 = blockIdx.x * 128;

    if (tid < 128) {
        float s = gam[tid] * rsqrtf(var[tid] + 1e-5f);
        sS[tid] = s;
        sO[tid] = (b_it[tid] - mu[tid]) * s + bet[tid];
    }

    const int m0 = wid * 16;
    float d[16][4];
    #pragma unroll
    for (int t = 0; t < 16; t++)
        #pragma unroll
        for (int j = 0; j < 4; j++) d[t][j] = 0.f;

    for (int kc = 0; kc < C2D; kc += 64) {
        __syncthreads();
        #pragma unroll
        for (int i = 0; i < 8; i++) {
            int idx = tid + i*256;
            int kk = idx >> 5, c4 = (idx & 31) << 2;
            float4 f = *(const float4*)&img[(size_t)((b*C2D + kc + kk))*HW + hw0 + c4];
            float* dst = &sImg[kk*IP + c4];
            dst[0] = to_tf32(f.x); dst[1] = to_tf32(f.y);
            dst[2] = to_tf32(f.z); dst[3] = to_tf32(f.w);
        }
        #pragma unroll
        for (int i = 0; i < 8; i++) {
            int idx = tid + i*256;
            int mid = idx & 127, kq = idx >> 7;
            float4 f = *(const float4*)&w_it[mid*C2D + kc + kq*4];
            sW[(kq*4+0)*IP + mid] = to_tf32(f.x);
            sW[(kq*4+1)*IP + mid] = to_tf32(f.y);
            sW[(kq*4+2)*IP + mid] = to_tf32(f.z);
            sW[(kq*4+3)*IP + mid] = to_tf32(f.w);
        }
        __syncthreads();
        const uint32_t* A = (const uint32_t*)sImg;
        const uint32_t* B = (const uint32_t*)sW;
        #pragma unroll
        for (int kc8 = 0; kc8 < 8; kc8++) {
            int k0 = kc8 * 8;
            uint32_t a0 = A[(k0+q)*IP   + m0 + p];
            uint32_t a1 = A[(k0+q)*IP   + m0 + 8 + p];
            uint32_t a2 = A[(k0+4+q)*IP + m0 + p];
            uint32_t a3 = A[(k0+4+q)*IP + m0 + 8 + p];
            #pragma unroll
            for (int t = 0; t < 16; t++) {
                int n0 = t*8;
                uint32_t b0 = B[(k0+q)*IP   + n0 + p];
                uint32_t b1 = B[(k0+4+q)*IP + n0 + p];
                mma8(d[t], a0, a1, a2, a3, b0, b1);
            }
        }
    }
    __syncthreads();   // last MMA done -> outS may overwrite sImg/sW

    #pragma unroll
    for (int t = 0; t < 16; t++) {
        int n0 = t*8;
        int c0 = n0 + 2*q, c1 = c0 + 1;
        int r0 = m0 + p,   r1 = r0 + 8;
        outS[r0*OSP + c0] = fmaxf(fmaf(d[t][0], sS[c0], sO[c0]), 0.f);
        outS[r0*OSP + c1] = fmaxf(fmaf(d[t][1], sS[c1], sO[c1]), 0.f);
        outS[r1*OSP + c0] = fmaxf(fmaf(d[t][2], sS[c0], sO[c0]), 0.f);
        outS[r1*OSP + c1] = fmaxf(fmaf(d[t][3], sS[c1], sO[c1]), 0.f);
    }
    __syncthreads();

    #pragma unroll
    for (int i = 0; i < 16; i++) {
        int idx = tid + i*256;           // 4096 float4s
        int r = idx >> 5, c4 = (idx & 31) << 2;
        float4 f = *(const float4*)&outS[r*OSP + c4];
        *(float4*)&g_itbuf[((size_t)b*HW + hw0 + r)*MIDC + c4] = f;
    }
}

// ---------------------------------------------------------------------------
// Kernel 2: fused pipeline, both GEMMs on mma.sync tf32.
// Stage-1b gather: 4-lanes-per-voxel contiguous 64B reads
// (8 lines/instr instead of 32) -> gather wavefronts 16.4K -> 6.1K.
// ---------------------------------------------------------------------------
#define FP     136              // fusedT / vfT / wvtT pitch (mod 32 == 8)
#define WFP    72               // wfT pitch (mod 32 == 8)
#define OTP    68               // outT pitch (multiple of 4)
#define SM2_BYTES (55808*4)

__global__ __launch_bounds__(512) void fuse_kernel(
    const float* __restrict__ vf,
    const int*   __restrict__ coords,
    const float* __restrict__ gt_boxes,
    const int*   __restrict__ gt_classes,
    const float* __restrict__ w_vt,
    const float* __restrict__ b_vt,
    const float* __restrict__ g_vt,
    const float* __restrict__ be_vt,
    const float* __restrict__ m_vt,
    const float* __restrict__ v_vt,
    const float* __restrict__ w_f,
    const float* __restrict__ b_f,
    const float* __restrict__ g_f,
    const float* __restrict__ be_f,
    const float* __restrict__ m_f,
    const float* __restrict__ v_f,
    float* __restrict__ out)
{
    extern __shared__ float sm[];
    float* fusedT  = sm;                  // [256][FP]
    float* vfT     = sm + 34816;          // [64][FP]
    float* wvtT    = sm + 43520;          // [64][FP]
    float* wfT     = sm + 34816;          // [256][WFP]  (alias, after stage 1)
    float* outT    = sm + 34816;          // [128][OTP]  (alias, after stage 2)
    float* boxes_s = sm + 53248;          // 896
    float* sA      = boxes_s + 896;       // 128
    float* oA      = sA + 128;            // 128
    float* sF      = oA + 128;            // 64
    float* oF      = sF + 64;             // 64
    float* w3d_s   = oF + 64;             // 128
    float* cw_s    = w3d_s + 128;         // 512
    int*   cls_s   = (int*)(cw_s + 512);  // 128
    int*   coff_s  = cls_s + 128;         // 512

    const int tid = threadIdx.x;
    const int wid = tid >> 5;
    const int lid = tid & 31;
    const int q   = lid & 3;     // threadID_in_group
    const int p   = lid >> 2;    // groupID
    const int v0  = blockIdx.x * 128;

    // ---- stage 0 loads ----
    for (int i = tid; i < 896; i += 512) boxes_s[i] = gt_boxes[i];
    if (tid < 128) {
        cls_s[tid] = gt_classes[tid];
        float s = g_vt[tid] * rsqrtf(v_vt[tid] + 1e-5f);
        sA[tid] = s;
        oA[tid] = (b_vt[tid] - m_vt[tid]) * s + be_vt[tid];
    } else if (tid < 192) {
        int c = tid - 128;
        float s = g_f[c] * rsqrtf(v_f[c] + 1e-5f);
        sF[c] = s;
        oF[c] = (b_f[c] - m_f[c]) * s + be_f[c];
    }
    // vfT[k][row] (tf32), pitch FP
    #pragma unroll
    for (int i = 0; i < 4; i++) {
        int idx = tid + i*512;
        int r = idx >> 4, k4 = (idx & 15) << 2;
        float4 f = *(const float4*)&vf[(size_t)(v0 + r)*C3D + k4];
        vfT[(k4+0)*FP + r] = to_tf32(f.x);
        vfT[(k4+1)*FP + r] = to_tf32(f.y);
        vfT[(k4+2)*FP + r] = to_tf32(f.z);
        vfT[(k4+3)*FP + r] = to_tf32(f.w);
    }
    // wvtT[k][mid] (tf32), pitch FP
    #pragma unroll
    for (int i = 0; i < 4; i++) {
        int idx = tid + i*512;
        int mid = idx & 127, kq = idx >> 7;
        float4 f = *(const float4*)&w_vt[mid*C3D + kq*4];
        wvtT[(kq*4+0)*FP + mid] = to_tf32(f.x);
        wvtT[(kq*4+1)*FP + mid] = to_tf32(f.y);
        wvtT[(kq*4+2)*FP + mid] = to_tf32(f.z);
        wvtT[(kq*4+3)*FP + mid] = to_tf32(f.w);
    }
    __syncthreads();

    // ---- stage 0b: per-voxel scalar work ----
    if (tid < 128) {
        int4 c = *(const int4*)&coords[(size_t)(v0 + tid)*4];
        int b = c.x;
        float crx = (float)c.w * 0.05f;
        float cry = (float)c.z * 0.05f - 40.f;
        float crz = (float)c.y * 0.1f  - 3.f;
        int last = -1;
        const float* bb = boxes_s + b*224;
        #pragma unroll
        for (int mi = 0; mi < NBOX; mi++) {
            const float* pb = bb + mi*7;
            bool in = (fabsf(crx - pb[0]) < pb[3]*0.5f) &&
                      (fabsf(cry - pb[1]) < pb[4]*0.5f) &&
                      (fabsf(crz - pb[2]) < pb[5]*0.5f) &&
                      (pb[3] > 0.f);
            if (in) last = mi;
        }
        float w3;
        if (last >= 0) {
            int cl = cls_s[b*NBOX + last];
            w3 = (cl == 0) ? 0.85f : ((cl == 1) ? 0.95f : 0.6f);
        } else w3 = 0.8f;
        w3d_s[tid] = w3;
        float cx = crx + 0.025f;
        float cy = cry + 0.025f;
        float px = cx*10.f + (float)IMW*0.5f;
        float py = cy*10.f + (float)IMH*0.5f;
        float nx = fminf(fmaxf(px/(float)IMW*2.f - 1.f, -1.f), 1.f);
        float ny = fminf(fmaxf(py/(float)IMH*2.f - 1.f, -1.f), 1.f);
        float fx = ((nx + 1.f)*(float)IMW - 1.f)*0.5f;
        float fy = ((ny + 1.f)*(float)IMH - 1.f)*0.5f;
        float x0f = floorf(fx), y0f = floorf(fy);
        float wx = fx - x0f, wy = fy - y0f;
        int x0 = (int)x0f, y0 = (int)y0f;
        #pragma unroll
        for (int ci = 0; ci < 4; ci++) {
            int dx = ci & 1, dy = ci >> 1;
            int xi = x0 + dx, yi = y0 + dy;
            bool val = (xi >= 0) && (xi < IMW) && (yi >= 0) && (yi < IMH);
            int xc = min(max(xi, 0), IMW-1);
            int yc = min(max(yi, 0), IMH-1);
            float wgt = (dx ? wx : 1.f - wx) * (dy ? wy : 1.f - wy);
            cw_s[tid*4 + ci]   = val ? wgt : 0.f;
            coff_s[tid*4 + ci] = ((b*IMH + yc)*IMW + xc) * MIDC;
        }
    }

    // ---- stage 1: vt GEMM via mma.sync tf32 (M128 N128 K64) ----
    const int m0 = (wid >> 1) * 16;
    const int nb = (wid & 1) * 64;
    float d1[8][4];
    #pragma unroll
    for (int t = 0; t < 8; t++)
        #pragma unroll
        for (int j = 0; j < 4; j++) d1[t][j] = 0.f;
    {
        const uint32_t* A = (const uint32_t*)vfT;
        const uint32_t* B = (const uint32_t*)wvtT;
        #pragma unroll
        for (int kc = 0; kc < 8; kc++) {
            int k0 = kc * 8;
            uint32_t a0 = A[(k0+q)*FP   + m0 + p];
            uint32_t a1 = A[(k0+q)*FP   + m0 + 8 + p];
            uint32_t a2 = A[(k0+4+q)*FP + m0 + p];
            uint32_t a3 = A[(k0+4+q)*FP + m0 + 8 + p];
            #pragma unroll
            for (int t = 0; t < 8; t++) {
                int n0 = nb + t*8;
                uint32_t b0 = B[(k0+q)*FP   + n0 + p];
                uint32_t b1 = B[(k0+4+q)*FP + n0 + p];
                mma8(d1[t], a0, a1, a2, a3, b0, b1);
            }
        }
    }
    __syncthreads();   // vfT/wvtT dead; w3d/cw/coff visible to all

    // ---- load w_f -> wfT[k][o] tf32, pitch WFP (aliases vfT/wvtT) ----
    #pragma unroll
    for (int i = 0; i < 8; i++) {
        int idx4 = tid + i*512;          // 4096 float4s
        int o  = idx4 >> 6;              // 0..63
        int kq = (idx4 & 63) << 2;       // 0..252
        float4 f = *(const float4*)&w_f[o*256 + kq];
        wfT[(kq+0)*WFP + o] = to_tf32(f.x);
        wfT[(kq+1)*WFP + o] = to_tf32(f.y);
        wfT[(kq+2)*WFP + o] = to_tf32(f.z);
        wfT[(kq+3)*WFP + o] = to_tf32(f.w);
    }

    // ---- stage 1 epilogue: bn+relu, * w3d -> fusedT (ch 0..127, k-major) ----
    #pragma unroll
    for (int t = 0; t < 8; t++) {
        int n0 = nb + t*8;
        int c0 = n0 + 2*q, c1 = c0 + 1;
        int r0 = m0 + p,   r1 = r0 + 8;
        float w30 = w3d_s[r0], w31 = w3d_s[r1];
        fusedT[c0*FP + r0] = to_tf32(fmaxf(fmaf(d1[t][0], sA[c0], oA[c0]), 0.f) * w30);
        fusedT[c1*FP + r0] = to_tf32(fmaxf(fmaf(d1[t][1], sA[c1], oA[c1]), 0.f) * w30);
        fusedT[c0*FP + r1] = to_tf32(fmaxf(fmaf(d1[t][2], sA[c0], oA[c0]), 0.f) * w31);
        fusedT[c1*FP + r1] = to_tf32(fmaxf(fmaf(d1[t][3], sA[c1], oA[c1]), 0.f) * w31);
    }

    // ---- stage 1b: bilinear sampling -> fusedT (ch 128..255) ----
    // Warp w owns voxels 8w..8w+7; 4 lanes per voxel read CONTIGUOUS
    // 64B chunks (pixel_base + j*64 + sub*16) -> 8 lines per LDG.128.
    // Lane (v, sub) covers channels {j*16 + sub*4 + e : j<8, e<4}.
    {
        int v   = 8*wid + (lid >> 2);     // voxel 0..127
        int sub = lid & 3;
        float wim = 1.f - w3d_s[v];
        float4 acc4[8];
        #pragma unroll
        for (int j = 0; j < 8; j++) acc4[j] = make_float4(0.f, 0.f, 0.f, 0.f);
        #pragma unroll
        for (int ci = 0; ci < 4; ci++) {
            float wgt = cw_s[v*4 + ci] * wim;
            const float4* pp = (const float4*)&g_itbuf[(size_t)coff_s[v*4 + ci]];
            #pragma unroll
            for (int j = 0; j < 8; j++) {
                float4 f = pp[j*4 + sub];
                acc4[j].x = fmaf(wgt, f.x, acc4[j].x);
                acc4[j].y = fmaf(wgt, f.y, acc4[j].y);
                acc4[j].z = fmaf(wgt, f.z, acc4[j].z);
                acc4[j].w = fmaf(wgt, f.w, acc4[j].w);
            }
        }
        #pragma unroll
        for (int j = 0; j < 8; j++) {
            int ch = 128 + j*16 + sub*4;
            fusedT[(ch+0)*FP + v] = to_tf32(acc4[j].x);
            fusedT[(ch+1)*FP + v] = to_tf32(acc4[j].y);
            fusedT[(ch+2)*FP + v] = to_tf32(acc4[j].z);
            fusedT[(ch+3)*FP + v] = to_tf32(acc4[j].w);
        }
    }
    __syncthreads();

    // ---- stage 2: final GEMM via mma.sync tf32 (M128 N64 K256) ----
    const int m0b = (wid & 7) * 16;
    const int nbb = (wid >> 3) * 32;
    float d2[4][4];
    #pragma unroll
    for (int t = 0; t < 4; t++)
        #pragma unroll
        for (int j = 0; j < 4; j++) d2[t][j] = 0.f;
    {
        const uint32_t* A = (const uint32_t*)fusedT;
        const uint32_t* B = (const uint32_t*)wfT;
        #pragma unroll 4
        for (int kc = 0; kc < 32; kc++) {
            int k0 = kc * 8;
            uint32_t a0 = A[(k0+q)*FP   + m0b + p];
            uint32_t a1 = A[(k0+q)*FP   + m0b + 8 + p];
            uint32_t a2 = A[(k0+4+q)*FP + m0b + p];
            uint32_t a3 = A[(k0+4+q)*FP + m0b + 8 + p];
            #pragma unroll
            for (int t = 0; t < 4; t++) {
                int n0 = nbb + t*8;
                uint32_t b0 = B[(k0+q)*WFP   + n0 + p];
                uint32_t b1 = B[(k0+4+q)*WFP + n0 + p];
                mma8(d2[t], a0, a1, a2, a3, b0, b1);
            }
        }
    }
    __syncthreads();   // wfT dead -> outT may overwrite

    // ---- epilogue 2a: bn+relu -> outT (row-major, pitch OTP) ----
    #pragma unroll
    for (int t = 0; t < 4; t++) {
        int n0 = nbb + t*8;
        int c0 = n0 + 2*q, c1 = c0 + 1;
        int r0 = m0b + p,  r1 = r0 + 8;
        outT[r0*OTP + c0] = fmaxf(fmaf(d2[t][0], sF[c0], oF[c0]), 0.f);
        outT[r0*OTP + c1] = fmaxf(fmaf(d2[t][1], sF[c1], oF[c1]), 0.f);
        outT[r1*OTP + c0] = fmaxf(fmaf(d2[t][2], sF[c0], oF[c0]), 0.f);
        outT[r1*OTP + c1] = fmaxf(fmaf(d2[t][3], sF[c1], oF[c1]), 0.f);
    }
    __syncthreads();

    // ---- epilogue 2b: coalesced float4 store to out ----
    #pragma unroll
    for (int i = 0; i < 4; i++) {
        int idx4 = tid + i*512;          // 2048 float4s
        int r = idx4 >> 4, c = (idx4 & 15) << 2;
        float4 f = *(const float4*)&outT[r*OTP + c];
        *(float4*)&out[(size_t)(v0 + r)*OUTC + c] = f;
    }
}

// ---------------------------------------------------------------------------
extern "C" void kernel_launch(void* const* d_in, const int* in_sizes, int n_in,
                              void* d_out, int out_size)
{
    const float* vf       = (const float*)d_in[0];
    const int*   coords   = (const int*)  d_in[1];
    const float* img      = (const float*)d_in[2];
    const float* boxes    = (const float*)d_in[3];
    const int*   classes  = (const int*)  d_in[4];
    const float* w_vt     = (const float*)d_in[5];
    const float* b_vt     = (const float*)d_in[6];
    const float* g_vt     = (const float*)d_in[7];
    const float* be_vt    = (const float*)d_in[8];
    const float* m_vt     = (const float*)d_in[9];
    const float* v_vt     = (const float*)d_in[10];
    const float* w_it     = (const float*)d_in[11];
    const float* b_it     = (const float*)d_in[12];
    const float* g_itp    = (const float*)d_in[13];
    const float* be_it    = (const float*)d_in[14];
    const float* m_it     = (const float*)d_in[15];
    const float* v_it     = (const float*)d_in[16];
    const float* w_f      = (const float*)d_in[17];
    const float* b_f      = (const float*)d_in[18];
    const float* g_f      = (const float*)d_in[19];
    const float* be_f     = (const float*)d_in[20];
    const float* m_f      = (const float*)d_in[21];
    const float* v_f      = (const float*)d_in[22];
    float* out = (float*)d_out;

    const size_t smem1 = (size_t)SM1_FLOATS * sizeof(float);   // 70,656 B
    cudaFuncSetAttribute(img_gemm_kernel,
                         cudaFuncAttributeMaxDynamicSharedMemorySize, (int)smem1);
    cudaFuncSetAttribute(fuse_kernel,
                         cudaFuncAttributeMaxDynamicSharedMemorySize, SM2_BYTES);

    img_gemm_kernel<<<dim3(HW/128, BATCH), 256, smem1>>>(
        img, w_it, b_it, g_itp, be_it, m_it, v_it);

    fuse_kernel<<<NVOX/128, 512, SM2_BYTES>>>(
        vf, coords, boxes, classes,
        w_vt, b_vt, g_vt, be_vt, m_vt, v_vt,
        w_f, b_f, g_f, be_f, m_f, v_f,
        out);
}